// round 5
// baseline (speedup 1.0000x reference)
#include <cuda_runtime.h>
#include <math.h>

#define BB 8
#define NN 2048
#define KKn 64
#define TUU 256

static __device__ __constant__ const float kRads[3] = {0.1f, 0.3f, 0.7f};
#define BN_SCALE_F 0.999500374687773f

// ---------------- scratch (device globals: allowed scratch path) ------------
__device__ float g_xm[BB * TUU];
__device__ float g_T[BB * 9];
__device__ float g_px[BB * NN];
__device__ float g_py[BB * NN];
__device__ float g_pz[BB * NN];
__device__ float g_bufA[(size_t)BB * NN * 576];  // feats / f2 / f4
__device__ float g_bufB[(size_t)BB * NN * 576];  // f1 / f3

// ---------------- packed fp32x2 helpers (sm_103a FFMA2 path) ----------------
__device__ __forceinline__ unsigned long long pk2(float a, float b) {
    unsigned long long r;
    asm("mov.b64 %0, {%1, %2};" : "=l"(r) : "f"(a), "f"(b));
    return r;
}
__device__ __forceinline__ void upk2(unsigned long long v, float& a, float& b) {
    float x, y;
    asm("mov.b64 {%0, %1}, %2;" : "=f"(x), "=f"(y) : "l"(v));
    a = x; b = y;
}
__device__ __forceinline__ unsigned long long ff2(unsigned long long a,
                                                  unsigned long long b,
                                                  unsigned long long c) {
    unsigned long long d;
    asm("fma.rn.f32x2 %0, %1, %2, %3;" : "=l"(d) : "l"(a), "l"(b), "l"(c));
    return d;
}

// ---------------- init: zero xm + output ------------------------------------
__global__ void initk(float* out) {
    int i = blockIdx.x * blockDim.x + threadIdx.x;
    if (i < BB * TUU) g_xm[i] = 0.f;
    if (i < BB * 170) out[i] = 0.f;
}

// ---------------- T-Net stage 1: relu(bn(points@tw+tb)) -> max over N -------
__global__ void tnet1(const float* __restrict__ points, const float* __restrict__ tw,
                      const float* __restrict__ tb, const float* __restrict__ tg1,
                      const float* __restrict__ tbt1) {
    int b = blockIdx.x, ch = blockIdx.y;
    __shared__ float sp[256 * 3];
    int base = (b * NN + ch * 256) * 3;
    for (int i = threadIdx.x; i < 768; i += 256) sp[i] = points[base + i];
    __syncthreads();
    int u = threadIdx.x;
    float w0 = tw[u], w1 = tw[256 + u], w2 = tw[512 + u], bz = tb[u];
    float ga = tg1[u] * BN_SCALE_F, be = tbt1[u];
    float m = 0.f;
    #pragma unroll 4
    for (int i = 0; i < 256; i++) {
        float x = sp[3 * i] * w0 + sp[3 * i + 1] * w1 + sp[3 * i + 2] * w2 + bz;
        x = fmaxf(x * ga + be, 0.f);
        m = fmaxf(m, x);
    }
    atomicMax((int*)&g_xm[b * 256 + u], __float_as_int(m));  // m >= 0: int-max valid
}

// ---------------- T-Net stage 2: dense -> dense -> 3x3 T --------------------
__global__ void tnet2(const float* __restrict__ td1w, const float* __restrict__ td1b,
                      const float* __restrict__ tg2, const float* __restrict__ tbt2,
                      const float* __restrict__ td2w, const float* __restrict__ td2b) {
    int b = blockIdx.x;
    __shared__ float xs[256], hs[256];
    int u = threadIdx.x;
    xs[u] = g_xm[b * 256 + u];
    __syncthreads();
    float acc = td1b[u];
    #pragma unroll 8
    for (int k = 0; k < 256; k++) acc += xs[k] * td1w[k * 256 + u];
    acc = acc * (tg2[u] * BN_SCALE_F) + tbt2[u];
    hs[u] = fmaxf(acc, 0.f);
    __syncthreads();
    if (u < 9) {
        float t = td2b[u];
        for (int k = 0; k < 256; k++) t += hs[k] * td2w[k * 9 + u];
        g_T[b * 9 + u] = t;
    }
}

// ---------------- apply T: pts = points @ T (SoA output) --------------------
__global__ void transformk(const float* __restrict__ points) {
    int gid = blockIdx.x * blockDim.x + threadIdx.x;
    if (gid >= BB * NN) return;
    int b = gid >> 11;
    const float* T = &g_T[b * 9];
    float p0 = points[gid * 3], p1 = points[gid * 3 + 1], p2 = points[gid * 3 + 2];
    g_px[gid] = p0 * T[0] + p1 * T[3] + p2 * T[6];
    g_py[gid] = p0 * T[1] + p1 * T[4] + p2 * T[7];
    g_pz[gid] = p0 * T[2] + p1 * T[5] + p2 * T[8];
}

// ---------------- ball-query top-K select + gather --------------------------
// One block per (b,n) row. Exact argsort(-score) semantics:
// key = (score_bits << 32) | ~j  => descending score, ascending index tiebreak.
// Histogram-threshold select (exact: buckets separate strictly by value),
// bitonic sort of <=512 survivors, zero-score fill by ascending index.
__global__ __launch_bounds__(256) void selectk(const float* __restrict__ noise) {
    __shared__ float spx[NN], spy[NN], spz[NN], sd[NN], snr[NN];
    __shared__ int hist[256];
    __shared__ unsigned long long cand[512];
    __shared__ int sel[3][64];
    __shared__ int sh_cnt, sh_b, sh_M;
    int b = blockIdx.x >> 11, n = blockIdx.x & 2047;
    int tid = threadIdx.x;
    const float* nr = noise + (size_t)(b * NN + n) * NN;
    for (int j = tid; j < NN; j += 256) {
        spx[j] = g_px[b * NN + j];
        spy[j] = g_py[b * NN + j];
        spz[j] = g_pz[b * NN + j];
        snr[j] = nr[j];
    }
    __syncthreads();
    float qx = spx[n], qy = spy[n], qz = spz[n];
    for (int j = tid; j < NN; j += 256) {
        float dx = qx - spx[j], dy = qy - spy[j], dz = qz - spz[j];
        sd[j] = sqrtf(dx * dx + dy * dy + dz * dz);
    }
    __syncthreads();

    for (int r = 0; r < 3; r++) {
        float rad = kRads[r];
        hist[tid] = 0;
        if (tid == 0) sh_cnt = 0;
        __syncthreads();
        for (int j = tid; j < NN; j += 256) {
            if (sd[j] <= rad && snr[j] > 0.f) {
                int bk = (int)(snr[j] * 256.f);
                if (bk > 255) bk = 255;
                atomicAdd(&hist[bk], 1);
            }
        }
        __syncthreads();
        if (tid == 0) {
            int cum = 0, bs = -1;
            for (int t = 255; t >= 0; t--) {
                cum += hist[t];
                if (bs < 0 && cum >= 64) bs = t;
            }
            sh_M = cum;
            sh_b = (bs < 0) ? 0 : bs;
        }
        __syncthreads();
        int bs = sh_b, M = sh_M;
        for (int j = tid; j < NN; j += 256) {
            if (sd[j] <= rad && snr[j] > 0.f) {
                int bk = (int)(snr[j] * 256.f);
                if (bk > 255) bk = 255;
                if (bk >= bs) {
                    int pos = atomicAdd(&sh_cnt, 1);
                    if (pos < 512)
                        cand[pos] = ((unsigned long long)__float_as_uint(snr[j]) << 32) |
                                    (unsigned int)(~j);
                }
            }
        }
        __syncthreads();
        int C = sh_cnt; if (C > 512) C = 512;
        int P = 64; while (P < C) P <<= 1;
        for (int i = C + tid; i < P; i += 256) cand[i] = 0ull;
        __syncthreads();
        // bitonic sort descending, P power of 2 (<=512)
        for (int size = 2; size <= P; size <<= 1) {
            for (int stride = size >> 1; stride > 0; stride >>= 1) {
                for (int i = tid; i < P; i += 256) {
                    int p = i ^ stride;
                    if (p > i) {
                        bool desc = ((i & size) == 0);
                        unsigned long long a = cand[i], c = cand[p];
                        if (desc ? (a < c) : (a > c)) { cand[i] = c; cand[p] = a; }
                    }
                }
                __syncthreads();
            }
        }
        int np = (M < 64) ? M : 64;
        if (tid < np) sel[r][tid] = (int)(~(unsigned int)(cand[tid] & 0xffffffffull));
        if (tid == 0 && np < 64) {
            // fill with score==0 entries (out of radius OR zero noise), index ascending
            int f = 0;
            for (int j = 0; j < NN && f < 64 - np; j++) {
                if (!(sd[j] <= rad && snr[j] > 0.f)) { sel[r][np + f] = j; f++; }
            }
        }
        __syncthreads();
    }
    // gather: feats[b,n, k*9 + r*3 + c] = pts[b, sel[r][k], c]
    float* out = &g_bufA[(size_t)(b * NN + n) * 576];
    for (int t = tid; t < 576; t += 256) {
        int k = t / 9, rem = t - 9 * k, r = rem / 3, c = rem - 3 * r;
        int j = sel[r][k];
        out[t] = (c == 0) ? spx[j] : ((c == 1) ? spy[j] : spz[j]);
    }
}

// ---------------- fused GEMM (+BN+ReLU / +residual / +max-reduce) -----------
// C[M,Nd] = epilogue(A[M,Kd] @ W[Kd,Nd]); 128x128x16 tile, 8x8/thread, FFMA2.
// mode 0: relu(bn(.)) -> other buffer
// mode 1: A + (.) + bias -> other buffer (residual)
// mode 2: relu(bn(.)) -> column-max over rows -> atomicMax into outx[B,Nd]
__global__ __launch_bounds__(256, 2) void gemmk(
    const float* __restrict__ W, const float* __restrict__ bias,
    const float* __restrict__ gamma, const float* __restrict__ beta,
    float* __restrict__ outx, int M, int Kd, int Nd, int mode, int srcB) {
    const float* A = srcB ? g_bufB : g_bufA;
    float* C = srcB ? g_bufA : g_bufB;
    __shared__ float As[16][128];
    __shared__ float Bs[16][128];
    __shared__ float colred[128];
    int tid = threadIdx.x;
    int tx = tid & 15, ty = tid >> 4;
    int bx = blockIdx.x, by = blockIdx.y;
    unsigned long long acc[8][4];
    #pragma unroll
    for (int i = 0; i < 8; i++)
        #pragma unroll
        for (int j = 0; j < 4; j++) acc[i][j] = 0ull;
    int nTiles = Kd >> 4;
    bool nd4 = (Nd & 3) == 0;
    for (int kt = 0; kt < nTiles; kt++) {
        __syncthreads();
        #pragma unroll
        for (int h = 0; h < 2; h++) {  // A tile: 128x16, transpose on store
            int q = tid + h * 256;
            int row = q >> 2, kc = (q & 3) << 2;
            float4 v = *reinterpret_cast<const float4*>(
                A + (size_t)(by * 128 + row) * Kd + kt * 16 + kc);
            As[kc + 0][row] = v.x; As[kc + 1][row] = v.y;
            As[kc + 2][row] = v.z; As[kc + 3][row] = v.w;
        }
        #pragma unroll
        for (int h = 0; h < 2; h++) {  // B tile: 16x128
            int q = tid + h * 256;
            int kl = q >> 5, nl = (q & 31) << 2;
            int colg = bx * 128 + nl;
            const float* wr = W + (size_t)(kt * 16 + kl) * Nd;
            float4 v;
            if (nd4 && colg + 3 < Nd) {
                v = *reinterpret_cast<const float4*>(wr + colg);
            } else {
                v.x = (colg + 0 < Nd) ? wr[colg + 0] : 0.f;
                v.y = (colg + 1 < Nd) ? wr[colg + 1] : 0.f;
                v.z = (colg + 2 < Nd) ? wr[colg + 2] : 0.f;
                v.w = (colg + 3 < Nd) ? wr[colg + 3] : 0.f;
            }
            *reinterpret_cast<float4*>(&Bs[kl][nl]) = v;
        }
        __syncthreads();
        #pragma unroll
        for (int kk = 0; kk < 16; kk++) {
            const float4* ap = reinterpret_cast<const float4*>(&As[kk][ty * 8]);
            float4 a0 = ap[0], a1 = ap[1];
            const float4* bp = reinterpret_cast<const float4*>(&Bs[kk][tx * 8]);
            float4 b0 = bp[0], b1 = bp[1];
            unsigned long long bb[4] = {pk2(b0.x, b0.y), pk2(b0.z, b0.w),
                                        pk2(b1.x, b1.y), pk2(b1.z, b1.w)};
            float av[8] = {a0.x, a0.y, a0.z, a0.w, a1.x, a1.y, a1.z, a1.w};
            #pragma unroll
            for (int i = 0; i < 8; i++) {
                unsigned long long ad = pk2(av[i], av[i]);
                #pragma unroll
                for (int j = 0; j < 4; j++) acc[i][j] = ff2(ad, bb[j], acc[i][j]);
            }
        }
    }
    // epilogue
    int col0 = bx * 128 + tx * 8;
    float bv[8], gav[8], bev[8];
    #pragma unroll
    for (int j = 0; j < 8; j++) {
        int c = col0 + j;
        bool ok = c < Nd;
        bv[j] = ok ? bias[c] : 0.f;
        if (mode != 1) {
            gav[j] = ok ? gamma[c] * BN_SCALE_F : 0.f;
            bev[j] = ok ? beta[c] : 0.f;
        }
    }
    if (mode == 2) {
        float cm[8];
        #pragma unroll
        for (int j = 0; j < 8; j++) cm[j] = 0.f;
        #pragma unroll
        for (int i = 0; i < 8; i++)
            #pragma unroll
            for (int jp = 0; jp < 4; jp++) {
                float lo, hi; upk2(acc[i][jp], lo, hi);
                cm[jp * 2] = fmaxf(cm[jp * 2],
                                   fmaxf((lo + bv[jp * 2]) * gav[jp * 2] + bev[jp * 2], 0.f));
                cm[jp * 2 + 1] = fmaxf(cm[jp * 2 + 1],
                                   fmaxf((hi + bv[jp * 2 + 1]) * gav[jp * 2 + 1] + bev[jp * 2 + 1], 0.f));
            }
        if (tid < 128) colred[tid] = 0.f;
        __syncthreads();
        #pragma unroll
        for (int j = 0; j < 8; j++)
            atomicMax((int*)&colred[tx * 8 + j], __float_as_int(cm[j]));
        __syncthreads();
        if (tid < 128) {
            int c = bx * 128 + tid;
            if (c < Nd) {
                int b = by >> 4;  // 2048 rows per batch / 128 rows per block
                atomicMax((int*)&outx[b * Nd + c], __float_as_int(colred[tid]));
            }
        }
        return;
    }
    #pragma unroll
    for (int i = 0; i < 8; i++) {
        int row = by * 128 + ty * 8 + i;
        size_t base = (size_t)row * Nd;
        #pragma unroll
        for (int jp = 0; jp < 4; jp++) {
            float lo, hi; upk2(acc[i][jp], lo, hi);
            int c0 = col0 + jp * 2;
            if (mode == 1) {
                lo = A[(size_t)row * Kd + c0] + lo + bv[jp * 2];
                hi = A[(size_t)row * Kd + c0 + 1] + hi + bv[jp * 2 + 1];
            } else {
                lo = fmaxf((lo + bv[jp * 2]) * gav[jp * 2] + bev[jp * 2], 0.f);
                hi = fmaxf((hi + bv[jp * 2 + 1]) * gav[jp * 2 + 1] + bev[jp * 2 + 1], 0.f);
            }
            if (c0 + 1 < Nd)
                *reinterpret_cast<float2*>(C + base + c0) = make_float2(lo, hi);
            else if (c0 < Nd)
                C[base + c0] = lo;
        }
    }
}

// ---------------- launch ----------------------------------------------------
extern "C" void kernel_launch(void* const* d_in, const int* in_sizes, int n_in,
                              void* d_out, int out_size) {
    const float* points = (const float*)d_in[0];
    const float* noise  = (const float*)d_in[1];
    const float* tw     = (const float*)d_in[2];
    const float* tb     = (const float*)d_in[3];
    const float* tg1    = (const float*)d_in[4];
    const float* tbt1   = (const float*)d_in[5];
    const float* td1w   = (const float*)d_in[6];
    const float* td1b   = (const float*)d_in[7];
    const float* tg2    = (const float*)d_in[8];
    const float* tbt2   = (const float*)d_in[9];
    const float* td2w   = (const float*)d_in[10];
    const float* td2b   = (const float*)d_in[11];
    const float* c1w    = (const float*)d_in[12];
    const float* c1b    = (const float*)d_in[13];
    const float* g1     = (const float*)d_in[14];
    const float* be1    = (const float*)d_in[15];
    const float* rw     = (const float*)d_in[16];
    const float* rb     = (const float*)d_in[17];
    const float* b1w    = (const float*)d_in[18];
    const float* b1b    = (const float*)d_in[19];
    const float* b1g    = (const float*)d_in[20];
    const float* b1be   = (const float*)d_in[21];
    const float* b2w    = (const float*)d_in[22];
    const float* b2b    = (const float*)d_in[23];
    const float* b2g    = (const float*)d_in[24];
    const float* b2be   = (const float*)d_in[25];
    const float* b3w    = (const float*)d_in[26];
    const float* b3b    = (const float*)d_in[27];
    const float* b3g    = (const float*)d_in[28];
    const float* b3be   = (const float*)d_in[29];
    float* out = (float*)d_out;
    const int M = BB * NN;

    initk<<<8, 256>>>(out);
    tnet1<<<dim3(8, 8), 256>>>(points, tw, tb, tg1, tbt1);
    tnet2<<<8, 256>>>(td1w, td1b, tg2, tbt2, td2w, td2b);
    transformk<<<64, 256>>>(points);
    selectk<<<BB * NN, 256>>>(noise);
    // feats(A) @ c1w -> f1(B)
    gemmk<<<dim3(4, 128), 256>>>(c1w, c1b, g1, be1, out, M, 576, 512, 0, 0);
    // f1(B) + f1@rw + rb -> f2(A)
    gemmk<<<dim3(4, 128), 256>>>(rw, rb, rb, rb, out, M, 512, 512, 1, 1);
    // f2(A) @ b1w -> f3(B)
    gemmk<<<dim3(4, 128), 256>>>(b1w, b1b, b1g, b1be, out, M, 512, 512, 0, 0);
    // f3(B) @ b2w -> f4(A)
    gemmk<<<dim3(2, 128), 256>>>(b2w, b2b, b2g, b2be, out, M, 512, 256, 0, 1);
    // f4(A) @ b3w -> max over N -> out[8,170]
    gemmk<<<dim3(2, 128), 256>>>(b3w, b3b, b3g, b3be, out, M, 256, 170, 2, 0);
}

// round 9
// speedup vs baseline: 1.4202x; 1.4202x over previous
#include <cuda_runtime.h>
#include <cuda_bf16.h>
#include <stdint.h>
#include <math.h>

#define BB 8
#define NN 2048
#define MM (BB * NN)
#define TUU 256
#define BN_SCALE_F 0.999500374687773f

static __device__ __constant__ const float kRads[3] = {0.1f, 0.3f, 0.7f};

// ---------------- scratch (device globals: allowed scratch path) ------------
__device__ float g_xm[BB * TUU];
__device__ float g_T[BB * 9];
__device__ float g_px[MM];
__device__ float g_py[MM];
__device__ float g_pz[MM];
__device__ __align__(16) float g_bufB[(size_t)MM * 512];   // f1 fp32 (residual src)
// bf16 hi/lo activation ping-pong
__device__ __align__(16) __nv_bfloat16 g_A0h[(size_t)MM * 576];
__device__ __align__(16) __nv_bfloat16 g_A0l[(size_t)MM * 576];
__device__ __align__(16) __nv_bfloat16 g_A1h[(size_t)MM * 576];
__device__ __align__(16) __nv_bfloat16 g_A1l[(size_t)MM * 576];
// transposed bf16 hi/lo weights, all 5 layers packed [Npad][K]
#define WTOT 1015808
__device__ __align__(16) __nv_bfloat16 g_Wh[WTOT];
__device__ __align__(16) __nv_bfloat16 g_Wl[WTOT];

// ---------------- baseline-ISA helpers (cp.async / ldmatrix / mma) ----------
__device__ __forceinline__ void cp16(uint32_t d, const void* s) {
    asm volatile("cp.async.cg.shared.global [%0], [%1], 16;" :: "r"(d), "l"(s));
}
#define LDMX4(R, addr) \
    asm volatile("ldmatrix.sync.aligned.m8n8.x4.shared.b16 {%0,%1,%2,%3}, [%4];" \
        : "=r"((R)[0]), "=r"((R)[1]), "=r"((R)[2]), "=r"((R)[3]) : "r"(addr))
#define MMA16(C, A, B) \
    asm volatile("mma.sync.aligned.m16n8k16.row.col.f32.bf16.bf16.f32 " \
        "{%0,%1,%2,%3}, {%4,%5,%6,%7}, {%8,%9}, {%0,%1,%2,%3};" \
        : "+f"((C)[0]), "+f"((C)[1]), "+f"((C)[2]), "+f"((C)[3]) \
        : "r"((A)[0]), "r"((A)[1]), "r"((A)[2]), "r"((A)[3]), \
          "r"((B)[0]), "r"((B)[1]))

// ---------------- init: zero xm + output ------------------------------------
__global__ void initk(float* out) {
    int i = blockIdx.x * blockDim.x + threadIdx.x;
    if (i < BB * TUU) g_xm[i] = 0.f;
    if (i < BB * 170) out[i] = 0.f;
}

// ---------------- T-Net stage 1 ---------------------------------------------
__global__ void tnet1(const float* __restrict__ points, const float* __restrict__ tw,
                      const float* __restrict__ tb, const float* __restrict__ tg1,
                      const float* __restrict__ tbt1) {
    int b = blockIdx.x, ch = blockIdx.y;
    __shared__ float sp[256 * 3];
    int base = (b * NN + ch * 256) * 3;
    for (int i = threadIdx.x; i < 768; i += 256) sp[i] = points[base + i];
    __syncthreads();
    int u = threadIdx.x;
    float w0 = tw[u], w1 = tw[256 + u], w2 = tw[512 + u], bz = tb[u];
    float ga = tg1[u] * BN_SCALE_F, be = tbt1[u];
    float m = 0.f;
    #pragma unroll 4
    for (int i = 0; i < 256; i++) {
        float x = sp[3 * i] * w0 + sp[3 * i + 1] * w1 + sp[3 * i + 2] * w2 + bz;
        x = fmaxf(x * ga + be, 0.f);
        m = fmaxf(m, x);
    }
    atomicMax((int*)&g_xm[b * 256 + u], __float_as_int(m));
}

// ---------------- T-Net stage 2 ---------------------------------------------
__global__ void tnet2(const float* __restrict__ td1w, const float* __restrict__ td1b,
                      const float* __restrict__ tg2, const float* __restrict__ tbt2,
                      const float* __restrict__ td2w, const float* __restrict__ td2b) {
    int b = blockIdx.x;
    __shared__ float xs[256], hs[256];
    int u = threadIdx.x;
    xs[u] = g_xm[b * 256 + u];
    __syncthreads();
    float acc = td1b[u];
    #pragma unroll 8
    for (int k = 0; k < 256; k++) acc += xs[k] * td1w[k * 256 + u];
    acc = acc * (tg2[u] * BN_SCALE_F) + tbt2[u];
    hs[u] = fmaxf(acc, 0.f);
    __syncthreads();
    if (u < 9) {
        float t = td2b[u];
        for (int k = 0; k < 256; k++) t += hs[k] * td2w[k * 9 + u];
        g_T[b * 9 + u] = t;
    }
}

// ---------------- apply T ----------------------------------------------------
__global__ void transformk(const float* __restrict__ points) {
    int gid = blockIdx.x * blockDim.x + threadIdx.x;
    if (gid >= MM) return;
    int b = gid >> 11;
    const float* T = &g_T[b * 9];
    float p0 = points[gid * 3], p1 = points[gid * 3 + 1], p2 = points[gid * 3 + 2];
    g_px[gid] = p0 * T[0] + p1 * T[3] + p2 * T[6];
    g_py[gid] = p0 * T[1] + p1 * T[4] + p2 * T[7];
    g_pz[gid] = p0 * T[2] + p1 * T[5] + p2 * T[8];
}

// ---------------- ball-query top-K select + gather (writes bf16 hi/lo) ------
__global__ __launch_bounds__(256) void selectk(const float* __restrict__ noise) {
    __shared__ float spx[NN], spy[NN], spz[NN], sd[NN], snr[NN];
    __shared__ int hist[256];
    __shared__ unsigned long long cand[512];
    __shared__ int sel[3][64];
    __shared__ int sh_cnt, sh_b, sh_M;
    int b = blockIdx.x >> 11, n = blockIdx.x & 2047;
    int tid = threadIdx.x;
    const float* nr = noise + (size_t)(b * NN + n) * NN;
    for (int j = tid; j < NN; j += 256) {
        spx[j] = g_px[b * NN + j];
        spy[j] = g_py[b * NN + j];
        spz[j] = g_pz[b * NN + j];
        snr[j] = nr[j];
    }
    __syncthreads();
    float qx = spx[n], qy = spy[n], qz = spz[n];
    for (int j = tid; j < NN; j += 256) {
        float dx = qx - spx[j], dy = qy - spy[j], dz = qz - spz[j];
        sd[j] = sqrtf(dx * dx + dy * dy + dz * dz);
    }
    __syncthreads();

    for (int r = 0; r < 3; r++) {
        float rad = kRads[r];
        hist[tid] = 0;
        if (tid == 0) sh_cnt = 0;
        __syncthreads();
        for (int j = tid; j < NN; j += 256) {
            if (sd[j] <= rad && snr[j] > 0.f) {
                int bk = (int)(snr[j] * 256.f);
                if (bk > 255) bk = 255;
                atomicAdd(&hist[bk], 1);
            }
        }
        __syncthreads();
        if (tid == 0) {
            int cum = 0, bs = -1;
            for (int t = 255; t >= 0; t--) {
                cum += hist[t];
                if (bs < 0 && cum >= 64) bs = t;
            }
            sh_M = cum;
            sh_b = (bs < 0) ? 0 : bs;
        }
        __syncthreads();
        int bs = sh_b, M = sh_M;
        for (int j = tid; j < NN; j += 256) {
            if (sd[j] <= rad && snr[j] > 0.f) {
                int bk = (int)(snr[j] * 256.f);
                if (bk > 255) bk = 255;
                if (bk >= bs) {
                    int pos = atomicAdd(&sh_cnt, 1);
                    if (pos < 512)
                        cand[pos] = ((unsigned long long)__float_as_uint(snr[j]) << 32) |
                                    (unsigned int)(~j);
                }
            }
        }
        __syncthreads();
        int C = sh_cnt; if (C > 512) C = 512;
        int P = 64; while (P < C) P <<= 1;
        for (int i = C + tid; i < P; i += 256) cand[i] = 0ull;
        __syncthreads();
        for (int size = 2; size <= P; size <<= 1) {
            for (int stride = size >> 1; stride > 0; stride >>= 1) {
                for (int i = tid; i < P; i += 256) {
                    int p = i ^ stride;
                    if (p > i) {
                        bool desc = ((i & size) == 0);
                        unsigned long long a = cand[i], c = cand[p];
                        if (desc ? (a < c) : (a > c)) { cand[i] = c; cand[p] = a; }
                    }
                }
                __syncthreads();
            }
        }
        int np = (M < 64) ? M : 64;
        if (tid < np) sel[r][tid] = (int)(~(unsigned int)(cand[tid] & 0xffffffffull));
        if (tid == 0 && np < 64) {
            int f = 0;
            for (int j = 0; j < NN && f < 64 - np; j++) {
                if (!(sd[j] <= rad && snr[j] > 0.f)) { sel[r][np + f] = j; f++; }
            }
        }
        __syncthreads();
    }
    // gather -> bf16 hi/lo feats (pair 0), row stride 576
    __nv_bfloat16* oh = &g_A0h[(size_t)(b * NN + n) * 576];
    __nv_bfloat16* ol = &g_A0l[(size_t)(b * NN + n) * 576];
    for (int t = tid; t < 576; t += 256) {
        int k = t / 9, rem = t - 9 * k, r = rem / 3, c = rem - 3 * r;
        int j = sel[r][k];
        float v = (c == 0) ? spx[j] : ((c == 1) ? spy[j] : spz[j]);
        __nv_bfloat16 h = __float2bfloat16(v);
        oh[t] = h;
        ol[t] = __float2bfloat16(v - __bfloat162float(h));
    }
}

// ---------------- weight prep: transpose + bf16 hi/lo split -----------------
__global__ void prepw(const float* __restrict__ W, int K, int N, int Npad, int off) {
    int idx = blockIdx.x * 256 + threadIdx.x;
    if (idx >= Npad * K) return;
    int n = idx / K, k = idx - n * K;
    float w = (n < N) ? W[(size_t)k * N + n] : 0.f;
    __nv_bfloat16 hi = __float2bfloat16(w);
    g_Wh[off + idx] = hi;
    g_Wl[off + idx] = __float2bfloat16(w - __bfloat162float(hi));
}

// ---------------- smem chunk loader (2-stage cp.async pipeline) -------------
// Stage layout: Ah @0, Al @10240, Bh @20480, Bl @30720; rows padded to 80B.
__device__ __forceinline__ void load_chunk(
    uint32_t dstb, const __nv_bfloat16* Ah, const __nv_bfloat16* Al,
    const __nv_bfloat16* Bh, const __nv_bfloat16* Bl,
    int m0, int n0, int K, int koff, int tid) {
    #pragma unroll
    for (int h = 0; h < 2; h++) {
        int gg = h * 256 + tid;
        int row = gg >> 2, seg = gg & 3;
        uint32_t doff = (uint32_t)(row * 80 + seg * 16);
        size_t aoff = (size_t)(m0 + row) * K + koff + seg * 8;
        size_t boff = (size_t)(n0 + row) * K + koff + seg * 8;
        cp16(dstb + doff,         Ah + aoff);
        cp16(dstb + 10240 + doff, Al + aoff);
        cp16(dstb + 20480 + doff, Bh + boff);
        cp16(dstb + 30720 + doff, Bl + boff);
    }
    asm volatile("cp.async.commit_group;" ::: "memory");
}

__device__ __forceinline__ void store_pair(__nv_bfloat16* Dh, __nv_bfloat16* Dl,
                                           size_t off, float y0, float y1) {
    __nv_bfloat16 h0 = __float2bfloat16(y0), h1 = __float2bfloat16(y1);
    __nv_bfloat16 l0 = __float2bfloat16(y0 - __bfloat162float(h0));
    __nv_bfloat16 l1 = __float2bfloat16(y1 - __bfloat162float(h1));
    *reinterpret_cast<__nv_bfloat162*>(Dh + off) = __halves2bfloat162(h0, h1);
    *reinterpret_cast<__nv_bfloat162*>(Dl + off) = __halves2bfloat162(l0, l1);
}

// ---------------- HMMA bf16x3 GEMM + fused epilogue -------------------------
// Block: 128x128, 8 warps (2x4), warp tile 64x32, mma.m16n8k16 bf16->f32.
// 3-product split: Ah*Bh + Ah*Bl + Al*Bh.
// mode 0: relu(bn) -> bf16 pair(dst) + fp32 g_bufB
// mode 1: g_bufB + acc + bias -> bf16 pair(dst)   (residual)
// mode 2: relu(bn) -> bf16 pair(dst)
// mode 3: relu(bn) -> col-max -> atomicMax outx[B,Nd]
__global__ __launch_bounds__(256, 2) void gemm_mma(
    int srcA, int K, int woff,
    const float* __restrict__ bias, const float* __restrict__ gamma,
    const float* __restrict__ beta, int mode, int Nd, int ldo,
    float* __restrict__ outx) {
    extern __shared__ __align__(16) char sm_[];
    __shared__ float sB[128], sG[128], sE[128];
    __shared__ int colred[128];
    int tid = threadIdx.x, lane = tid & 31, wid = tid >> 5;
    int wm = wid >> 2, wn = wid & 3;
    int m0 = blockIdx.y * 128, n0 = blockIdx.x * 128;
    const __nv_bfloat16* Ah = srcA ? g_A1h : g_A0h;
    const __nv_bfloat16* Al = srcA ? g_A1l : g_A0l;
    __nv_bfloat16* Dh = srcA ? g_A0h : g_A1h;
    __nv_bfloat16* Dl = srcA ? g_A0l : g_A1l;
    const __nv_bfloat16* Wh = g_Wh + woff;
    const __nv_bfloat16* Wl = g_Wl + woff;

    if (tid < 128) {
        int c = n0 + tid;
        if (c < Nd) {
            sB[tid] = bias[c];
            sG[tid] = (mode == 1) ? 0.f : gamma[c] * BN_SCALE_F;
            sE[tid] = (mode == 1) ? 0.f : beta[c];
        } else { sB[tid] = sG[tid] = sE[tid] = 0.f; }
        colred[tid] = 0;
    }

    uint32_t sb = (uint32_t)__cvta_generic_to_shared(sm_);
    float acc[4][4][4];
    #pragma unroll
    for (int i = 0; i < 4; i++)
        #pragma unroll
        for (int j = 0; j < 4; j++)
            #pragma unroll
            for (int q = 0; q < 4; q++) acc[i][j][q] = 0.f;

    int nCh = K >> 5;
    load_chunk(sb, Ah, Al, Wh, Wl, m0, n0, K, 0, tid);
    for (int kt = 0; kt < nCh; kt++) {
        uint32_t stb = sb + (uint32_t)((kt & 1) * 40960);
        if (kt + 1 < nCh) {
            load_chunk(sb + (uint32_t)(((kt + 1) & 1) * 40960),
                       Ah, Al, Wh, Wl, m0, n0, K, (kt + 1) * 32, tid);
            asm volatile("cp.async.wait_group 1;" ::: "memory");
        } else {
            asm volatile("cp.async.wait_group 0;" ::: "memory");
        }
        __syncthreads();
        #pragma unroll
        for (int sub = 0; sub < 2; sub++) {
            uint32_t a[4][4], bh[4][2], bl[4][2];
            #pragma unroll
            for (int n2 = 0; n2 < 2; n2++) {
                uint32_t r4[4];
                uint32_t bd = stb + 20480 +
                    (uint32_t)((wn * 32 + n2 * 16 + ((lane >> 4) & 1) * 8 + (lane & 7)) * 80) +
                    (uint32_t)(((lane >> 3) & 1) * 16 + sub * 32);
                LDMX4(r4, bd);
                bh[n2 * 2][0] = r4[0]; bh[n2 * 2][1] = r4[1];
                bh[n2 * 2 + 1][0] = r4[2]; bh[n2 * 2 + 1][1] = r4[3];
                LDMX4(r4, bd + 10240);
                bl[n2 * 2][0] = r4[0]; bl[n2 * 2][1] = r4[1];
                bl[n2 * 2 + 1][0] = r4[2]; bl[n2 * 2 + 1][1] = r4[3];
            }
            #pragma unroll
            for (int mt = 0; mt < 4; mt++) {
                uint32_t ad = stb +
                    (uint32_t)((wm * 64 + mt * 16 + (lane & 15)) * 80) +
                    (uint32_t)(((lane >> 4) & 1) * 16 + sub * 32);
                LDMX4(a[mt], ad);
            }
            #pragma unroll
            for (int mt = 0; mt < 4; mt++)
                #pragma unroll
                for (int nt = 0; nt < 4; nt++) {
                    MMA16(acc[mt][nt], a[mt], bh[nt]);
                    MMA16(acc[mt][nt], a[mt], bl[nt]);
                }
            #pragma unroll
            for (int mt = 0; mt < 4; mt++) {
                uint32_t ad = stb + 10240 +
                    (uint32_t)((wm * 64 + mt * 16 + (lane & 15)) * 80) +
                    (uint32_t)(((lane >> 4) & 1) * 16 + sub * 32);
                LDMX4(a[mt], ad);
            }
            #pragma unroll
            for (int mt = 0; mt < 4; mt++)
                #pragma unroll
                for (int nt = 0; nt < 4; nt++) MMA16(acc[mt][nt], a[mt], bh[nt]);
        }
        __syncthreads();
    }

    // ---- epilogue ----
    int g = lane >> 2, tg = lane & 3;
    #pragma unroll
    for (int mt = 0; mt < 4; mt++) {
        int r0 = m0 + wm * 64 + mt * 16 + g;
        #pragma unroll
        for (int nt = 0; nt < 4; nt++) {
            int cl = wn * 32 + nt * 8 + tg * 2;
            int c0 = n0 + cl;
            float v00 = acc[mt][nt][0], v01 = acc[mt][nt][1];
            float v10 = acc[mt][nt][2], v11 = acc[mt][nt][3];
            if (mode == 3) {
                float y00 = fmaxf(fmaf(v00 + sB[cl], sG[cl], sE[cl]), 0.f);
                float y10 = fmaxf(fmaf(v10 + sB[cl], sG[cl], sE[cl]), 0.f);
                float y01 = fmaxf(fmaf(v01 + sB[cl + 1], sG[cl + 1], sE[cl + 1]), 0.f);
                float y11 = fmaxf(fmaf(v11 + sB[cl + 1], sG[cl + 1], sE[cl + 1]), 0.f);
                if (c0 < Nd)
                    atomicMax(&colred[cl], __float_as_int(fmaxf(y00, y10)));
                if (c0 + 1 < Nd)
                    atomicMax(&colred[cl + 1], __float_as_int(fmaxf(y01, y11)));
            } else if (mode == 1) {
                float2 f0 = *reinterpret_cast<const float2*>(&g_bufB[(size_t)r0 * 512 + c0]);
                float2 f1 = *reinterpret_cast<const float2*>(&g_bufB[(size_t)(r0 + 8) * 512 + c0]);
                store_pair(Dh, Dl, (size_t)r0 * ldo + c0,
                           f0.x + v00 + sB[cl], f0.y + v01 + sB[cl + 1]);
                store_pair(Dh, Dl, (size_t)(r0 + 8) * ldo + c0,
                           f1.x + v10 + sB[cl], f1.y + v11 + sB[cl + 1]);
            } else {
                float y00 = fmaxf(fmaf(v00 + sB[cl], sG[cl], sE[cl]), 0.f);
                float y01 = fmaxf(fmaf(v01 + sB[cl + 1], sG[cl + 1], sE[cl + 1]), 0.f);
                float y10 = fmaxf(fmaf(v10 + sB[cl], sG[cl], sE[cl]), 0.f);
                float y11 = fmaxf(fmaf(v11 + sB[cl + 1], sG[cl + 1], sE[cl + 1]), 0.f);
                store_pair(Dh, Dl, (size_t)r0 * ldo + c0, y00, y01);
                store_pair(Dh, Dl, (size_t)(r0 + 8) * ldo + c0, y10, y11);
                if (mode == 0) {
                    *reinterpret_cast<float2*>(&g_bufB[(size_t)r0 * 512 + c0]) =
                        make_float2(y00, y01);
                    *reinterpret_cast<float2*>(&g_bufB[(size_t)(r0 + 8) * 512 + c0]) =
                        make_float2(y10, y11);
                }
            }
        }
    }
    if (mode == 3) {
        __syncthreads();
        if (tid < 128) {
            int c = n0 + tid;
            if (c < Nd) {
                int b = m0 >> 11;
                atomicMax((int*)&outx[b * Nd + c], colred[tid]);
            }
        }
    }
}

// ---------------- launch ----------------------------------------------------
extern "C" void kernel_launch(void* const* d_in, const int* in_sizes, int n_in,
                              void* d_out, int out_size) {
    const float* points = (const float*)d_in[0];
    const float* noise  = (const float*)d_in[1];
    const float* tw     = (const float*)d_in[2];
    const float* tb     = (const float*)d_in[3];
    const float* tg1    = (const float*)d_in[4];
    const float* tbt1   = (const float*)d_in[5];
    const float* td1w   = (const float*)d_in[6];
    const float* td1b   = (const float*)d_in[7];
    const float* tg2    = (const float*)d_in[8];
    const float* tbt2   = (const float*)d_in[9];
    const float* td2w   = (const float*)d_in[10];
    const float* td2b   = (const float*)d_in[11];
    const float* c1w    = (const float*)d_in[12];
    const float* c1b    = (const float*)d_in[13];
    const float* g1     = (const float*)d_in[14];
    const float* be1    = (const float*)d_in[15];
    const float* rw     = (const float*)d_in[16];
    const float* rb     = (const float*)d_in[17];
    const float* b1w    = (const float*)d_in[18];
    const float* b1b    = (const float*)d_in[19];
    const float* b1g    = (const float*)d_in[20];
    const float* b1be   = (const float*)d_in[21];
    const float* b2w    = (const float*)d_in[22];
    const float* b2b    = (const float*)d_in[23];
    const float* b2g    = (const float*)d_in[24];
    const float* b2be   = (const float*)d_in[25];
    const float* b3w    = (const float*)d_in[26];
    const float* b3b    = (const float*)d_in[27];
    const float* b3g    = (const float*)d_in[28];
    const float* b3be   = (const float*)d_in[29];
    float* out = (float*)d_out;

    initk<<<8, 256>>>(out);
    tnet1<<<dim3(8, 8), 256>>>(points, tw, tb, tg1, tbt1);
    tnet2<<<8, 256>>>(td1w, td1b, tg2, tbt2, td2w, td2b);
    transformk<<<64, 256>>>(points);
    // weight prep (independent of select)
    prepw<<<(512 * 576 + 255) / 256, 256>>>(c1w, 576, 512, 512, 0);
    prepw<<<(512 * 512 + 255) / 256, 256>>>(rw,  512, 512, 512, 294912);
    prepw<<<(512 * 512 + 255) / 256, 256>>>(b1w, 512, 512, 512, 557056);
    prepw<<<(256 * 512 + 255) / 256, 256>>>(b2w, 512, 256, 256, 819200);
    prepw<<<(256 * 256 + 255) / 256, 256>>>(b3w, 256, 170, 256, 950272);
    selectk<<<MM, 256>>>(noise);

    const int dyn = 81920;  // 2 stages x 40960B
    cudaFuncSetAttribute(gemm_mma, cudaFuncAttributeMaxDynamicSharedMemorySize, dyn);
    // L1: pair0 (K=576) @ c1w -> relu/bn -> pair1 + f1 fp32
    gemm_mma<<<dim3(4, 128), 256, dyn>>>(0, 576, 0,      c1b, g1,  be1,  0, 512, 512, nullptr);
    // L2: pair1 @ rw, residual f1 + . + rb -> pair0
    gemm_mma<<<dim3(4, 128), 256, dyn>>>(1, 512, 294912, rb,  rb,  rb,   1, 512, 512, nullptr);
    // L3: pair0 @ b1w -> relu/bn -> pair1
    gemm_mma<<<dim3(4, 128), 256, dyn>>>(0, 512, 557056, b1b, b1g, b1be, 2, 512, 512, nullptr);
    // L4: pair1 @ b2w -> relu/bn -> pair0 (ldo 256)
    gemm_mma<<<dim3(2, 128), 256, dyn>>>(1, 512, 819200, b2b, b2g, b2be, 2, 256, 256, nullptr);
    // L5: pair0 (K=256) @ b3w(pad 256) -> relu/bn -> col-max -> out[8,170]
    gemm_mma<<<dim3(2, 128), 256, dyn>>>(0, 256, 950272, b3b, b3g, b3be, 3, 170, 0,   out);
}